// round 16
// baseline (speedup 1.0000x reference)
#include <cuda_runtime.h>

#define S_LEN   2048
#define NCH     64
#define NB      16
#define CHUNK   128
#define NSC     (S_LEN / CHUNK)        // 16 sample-chunks
#define PLI_THREADS 512
#define NWARPS  (PLI_THREADS / 32)
#define FFT_THREADS 512

// Scratch (static __device__ allocation — allowed by harness rules)
__device__ float2 g_analytic[NB * NCH * S_LEN];   // 16 MB
__device__ int    g_cnt[NB * NCH * NCH];          // 256 KB of int counters

// ---------------------------------------------------------------------------
// Packed f32x2 helpers (Blackwell sm_103a): one op = two fp32 lanes.
// ---------------------------------------------------------------------------
__device__ __forceinline__ unsigned long long mul2(unsigned long long a,
                                                   unsigned long long b) {
    unsigned long long d;
    asm("mul.rn.f32x2 %0, %1, %2;" : "=l"(d) : "l"(a), "l"(b));
    return d;
}
__device__ __forceinline__ unsigned long long fma2(unsigned long long a,
                                                   unsigned long long b,
                                                   unsigned long long c) {
    unsigned long long d;
    asm("fma.rn.f32x2 %0, %1, %2, %3;" : "=l"(d) : "l"(a), "l"(b), "l"(c));
    return d;
}

// ---------------------------------------------------------------------------
// Radix-4 Stockham autosort FFT pieces (N = 2048 = 2 * 4^5).
// DIF formulation; natural-order in, natural-order out; ping-pong buffers.
// ---------------------------------------------------------------------------
__device__ __forceinline__ float2 cmul(float2 a, float2 b) {
    return make_float2(fmaf(a.x, b.x, -a.y * b.y),
                       fmaf(a.x, b.y,  a.y * b.x));
}

// radix-2 first stage (forward): l = 1024, m = 1
__device__ __forceinline__ void stage_r2_fwd(const float2* __restrict__ src,
                                             float2* __restrict__ dst,
                                             const float2* __restrict__ tw,
                                             int tid) {
    #pragma unroll
    for (int p = tid; p < 1024; p += FFT_THREADS) {
        float2 w = tw[p];                       // exp(-2*pi*i p/2048)
        float2 a = src[p];
        float2 b = src[p + 1024];
        dst[2 * p]     = make_float2(a.x + b.x, a.y + b.y);
        dst[2 * p + 1] = cmul(w, make_float2(a.x - b.x, a.y - b.y));
    }
}

// radix-4 stage: L * M * 4 == 2048
template<int L, int LOG2M, bool INV>
__device__ __forceinline__ void stage_r4(const float2* __restrict__ src,
                                         float2* __restrict__ dst,
                                         const float2* __restrict__ tw,
                                         int tid) {
    constexpr int M   = 1 << LOG2M;
    constexpr int TWS = 512 / L;                // twiddle stride
    #pragma unroll
    for (int t = tid; t < 512; t += FFT_THREADS) {
        const int p = t >> LOG2M;
        const int q = t & (M - 1);
        const int ib = q + M * p;               // == t
        float2 a = src[ib];
        float2 b = src[ib + M * L];
        float2 c = src[ib + 2 * M * L];
        float2 d = src[ib + 3 * M * L];

        float2 w1 = tw[p * TWS];                // exp(-2*pi*i p/(4L))
        float2 w2 = tw[2 * p * TWS];
        if (INV) { w1.y = -w1.y; w2.y = -w2.y; }
        float2 w3 = cmul(w1, w2);

        float2 t0 = make_float2(a.x + c.x, a.y + c.y);
        float2 t1 = make_float2(a.x - c.x, a.y - c.y);
        float2 t2 = make_float2(b.x + d.x, b.y + d.y);
        float2 e  = make_float2(b.x - d.x, b.y - d.y);
        float2 t3 = INV ? make_float2(-e.y,  e.x)
                        : make_float2( e.y, -e.x);

        const int ob = q + 4 * M * p;
        dst[ob]         = make_float2(t0.x + t2.x, t0.y + t2.y);
        dst[ob + M]     = cmul(w1, make_float2(t1.x + t3.x, t1.y + t3.y));
        dst[ob + 2 * M] = cmul(w2, make_float2(t0.x - t2.x, t0.y - t2.y));
        dst[ob + 3 * M] = cmul(w3, make_float2(t1.x - t3.x, t1.y - t3.y));
    }
}

// 5 inverse radix-4 stages (after the fused degenerate stage-1).
// X -> Y -> X -> Y -> X -> Y : result lands in Y. Ends with __syncthreads.
__device__ __forceinline__ void ifft_tail(float2* __restrict__ X,
                                          float2* __restrict__ Y,
                                          const float2* __restrict__ tw,
                                          int tid) {
    stage_r4<256, 1, true>(X, Y, tw, tid);  __syncthreads();
    stage_r4< 64, 3, true>(Y, X, tw, tid);  __syncthreads();
    stage_r4< 16, 5, true>(X, Y, tw, tid);  __syncthreads();
    stage_r4<  4, 7, true>(Y, X, tw, tid);  __syncthreads();
    stage_r4<  1, 9, true>(X, Y, tw, tid);  __syncthreads();
}

// ---------------------------------------------------------------------------
// Kernel 1: Hilbert analytic signal (unchanged from R15 winner).
//   W = IFFT(h/N ⊙ FFT(x0 + i*x1));  Hx0 = Im W - x1 ,  Hx1 = x0 - Re W.
// Single inverse chain; degenerate stage-1 fused with the filter.
// Also zeroes g_cnt (stream-ordered before pli).
// ---------------------------------------------------------------------------
__global__ __launch_bounds__(FFT_THREADS)
void hilbert_kernel(const float* __restrict__ x) {
    __shared__ float2 A [S_LEN];
    __shared__ float2 B [S_LEN];
    __shared__ float2 tw[S_LEN / 2];

    const int bc  = blockIdx.x;               // 0..511 (channel pair)
    const int tid = threadIdx.x;
    const int ch0 = 2 * bc;

    if (tid < 128) g_cnt[bc * 128 + tid] = 0;

    const float* __restrict__ x0 = x + (size_t)ch0 * S_LEN;
    const float* __restrict__ x1 = x0 + S_LEN;

    for (int k = tid; k < S_LEN / 2; k += FFT_THREADS) {
        float ang = (-6.283185307179586f / (float)S_LEN) * (float)k;
        float sn, cs;
        sincosf(ang, &sn, &cs);
        tw[k] = make_float2(cs, sn);
    }
    for (int i = tid; i < S_LEN; i += FFT_THREADS)
        A[i] = make_float2(x0[i], x1[i]);
    __syncthreads();

    stage_r2_fwd(A, B, tw, tid);               __syncthreads();
    stage_r4<256, 1, false>(B, A, tw, tid);    __syncthreads();
    stage_r4< 64, 3, false>(A, B, tw, tid);    __syncthreads();
    stage_r4< 16, 5, false>(B, A, tw, tid);    __syncthreads();
    stage_r4<  4, 7, false>(A, B, tw, tid);    __syncthreads();
    stage_r4<  1, 9, false>(B, A, tw, tid);    __syncthreads();

    const float S0 = 1.0f / 2048.0f;
    const float S1 = 2.0f / 2048.0f;
    for (int p = tid; p < 1024; p += FFT_THREADS) {
        if (p == 0) {
            float2 z0 = A[0];
            float2 zn = A[1024];
            float2 W0 = make_float2(z0.x * S0, z0.y * S0);
            float2 Wn = make_float2(zn.x * S0, zn.y * S0);
            B[0] = make_float2(W0.x + Wn.x, W0.y + Wn.y);
            B[1] = make_float2(W0.x - Wn.x, W0.y - Wn.y);
        } else {
            float2 zp = A[p];
            float2 Wp = make_float2(zp.x * S1, zp.y * S1);
            float2 wc = tw[p]; wc.y = -wc.y;
            B[2 * p]     = Wp;
            B[2 * p + 1] = cmul(wc, Wp);
        }
    }
    __syncthreads();

    ifft_tail(B, A, tw, tid);

    float2* __restrict__ d0 = g_analytic + (size_t)ch0 * S_LEN;
    float2* __restrict__ d1 = d0 + S_LEN;
    for (int i = tid; i < S_LEN; i += FFT_THREADS) {
        float2 W  = A[i];
        float  r0 = x0[i];
        float  r1 = x1[i];
        d0[i] = make_float2(r0, W.y - r1);
        d1[i] = make_float2(r1, r0 - W.x);
    }
}

// ---------------------------------------------------------------------------
// Kernel 2: pairwise sign counting with packed f32x2 math.
// SoA smem (X rows / Y rows, 64 KB total): a lane's LDS.128 gives 4
// consecutive samples of one component, pre-packed for f32x2.
// Per pair-pack: cross2 = fma2(yi, xj, mul2(-xi, yj)) — bit-identical
// rounding to the scalar FMUL+FFMA path — then two sign-bit accumulates.
// Epilogue (REDUX + lane-0 atomics) unchanged from the R11/R15 winner.
// ---------------------------------------------------------------------------
__global__ __launch_bounds__(PLI_THREADS)
void pli_kernel() {
    extern __shared__ float sp[];
    float* SX = sp;                        // [NCH][CHUNK]
    float* SY = sp + NCH * CHUNK;          // [NCH][CHUNK]
    const int sc  = blockIdx.x;
    const int b   = blockIdx.y;
    const int tid = threadIdx.x;

    // stage: deinterleave float2 stream into X / Y rows (float4 reads,
    // float2 writes — conflict-free, coalesced)
    const float4* gsrc = reinterpret_cast<const float4*>(g_analytic);
    for (int k = tid; k < NCH * (CHUNK / 2); k += PLI_THREADS) {
        int c  = k >> 6;                   // CHUNK/2 = 64 sample-pairs/row
        int spp = k & 63;
        float4 v = gsrc[(((size_t)(b * NCH + c)) * S_LEN + (size_t)sc * CHUNK) / 2 + spp];
        reinterpret_cast<float2*>(SX + c * CHUNK)[spp] = make_float2(v.x, v.z);
        reinterpret_cast<float2*>(SY + c * CHUNK)[spp] = make_float2(v.y, v.w);
    }
    __syncthreads();

    const int warp = tid >> 5;
    const int lane = tid & 31;
    const unsigned long long NEGM = 0x8000000080000000ULL;

    for (int t = warp; t < 136; t += NWARPS) {
        int ti = 0, rem = t;
        while (rem >= (16 - ti)) { rem -= (16 - ti); ti++; }
        int tj = ti + rem;

        // lane covers samples 4*lane .. 4*lane+3 of the chunk (all 128
        // samples in one pass; two ull packs per float4)
        const float4* RXi = reinterpret_cast<const float4*>(SX + (ti * 4) * CHUNK) + lane;
        const float4* RYi = reinterpret_cast<const float4*>(SY + (ti * 4) * CHUNK) + lane;
        const float4* RXj = reinterpret_cast<const float4*>(SX + (tj * 4) * CHUNK) + lane;
        const float4* RYj = reinterpret_cast<const float4*>(SY + (tj * 4) * CHUNK) + lane;
        const int RS = CHUNK / 4;          // row stride in float4

        // i-side: load and pre-negate x
        unsigned long long nxi[4][2], yi[4][2];
        #pragma unroll
        for (int a = 0; a < 4; a++) {
            float4 xv = RXi[a * RS];
            float4 yv = RYi[a * RS];
            const unsigned long long* xp = reinterpret_cast<const unsigned long long*>(&xv);
            const unsigned long long* yp = reinterpret_cast<const unsigned long long*>(&yv);
            nxi[a][0] = xp[0] ^ NEGM;  nxi[a][1] = xp[1] ^ NEGM;
            yi [a][0] = yp[0];         yi [a][1] = yp[1];
        }

        unsigned acc[16];
        #pragma unroll
        for (int q = 0; q < 16; q++) acc[q] = 0u;

        #pragma unroll
        for (int c2 = 0; c2 < 4; c2++) {
            float4 xv = RXj[c2 * RS];
            float4 yv = RYj[c2 * RS];
            const unsigned long long* xp = reinterpret_cast<const unsigned long long*>(&xv);
            const unsigned long long* yp = reinterpret_cast<const unsigned long long*>(&yv);
            unsigned long long xj0 = xp[0], xj1 = xp[1];
            unsigned long long yj0 = yp[0], yj1 = yp[1];

            #pragma unroll
            for (int a = 0; a < 4; a++) {
                // cross = yi*xj + (-xi)*yj  (two samples per op)
                unsigned long long c0 = fma2(yi[a][0], xj0, mul2(nxi[a][0], yj0));
                unsigned long long c1 = fma2(yi[a][1], xj1, mul2(nxi[a][1], yj1));
                unsigned q0 = (unsigned)c0, q1 = (unsigned)(c0 >> 32);
                unsigned q2 = (unsigned)c1, q3 = (unsigned)(c1 >> 32);
                acc[a * 4 + c2] += (q0 >> 31) + (q1 >> 31)
                                 + (q2 >> 31) + (q3 >> 31);
            }
        }

        #pragma unroll
        for (int q = 0; q < 16; q++)
            acc[q] = __reduce_add_sync(0xffffffffu, acc[q]);

        if (lane == 0) {
            #pragma unroll
            for (int a = 0; a < 4; a++) {
                #pragma unroll
                for (int c2 = 0; c2 < 4; c2++) {
                    atomicAdd(&g_cnt[(b * NCH + ti * 4 + a) * NCH + tj * 4 + c2],
                              (int)acc[a * 4 + c2]);
                }
            }
        }
    }
}

// ---------------------------------------------------------------------------
// Kernel 3: finalize |2c - S|/S ; zero diagonal; mirror i>j.
// ---------------------------------------------------------------------------
__global__ void finalize_kernel(float* __restrict__ out) {
    int idx = blockIdx.x * blockDim.x + threadIdx.x;
    if (idx >= NB * NCH * NCH) return;
    int b = idx >> 12;
    int i = (idx >> 6) & 63;
    int j = idx & 63;
    float v = 0.0f;
    if (i != j) {
        int c = (i < j) ? g_cnt[(b * NCH + i) * NCH + j]
                        : g_cnt[(b * NCH + j) * NCH + i];
        v = fabsf(2.0f * (float)c - (float)S_LEN) * (1.0f / (float)S_LEN);
    }
    out[idx] = v;
}

// ---------------------------------------------------------------------------
extern "C" void kernel_launch(void* const* d_in, const int* in_sizes, int n_in,
                              void* d_out, int out_size) {
    const float* x = (const float*)d_in[0];
    float* out = (float*)d_out;
    (void)in_sizes; (void)n_in; (void)out_size;

    const int pli_smem = 2 * NCH * CHUNK * (int)sizeof(float);  // 64 KB
    cudaFuncSetAttribute(pli_kernel,
                         cudaFuncAttributeMaxDynamicSharedMemorySize, pli_smem);

    hilbert_kernel<<<NB * NCH / 2, FFT_THREADS>>>(x);
    pli_kernel<<<dim3(NSC, NB), PLI_THREADS, pli_smem>>>();
    finalize_kernel<<<(NB * NCH * NCH + 255) / 256, 256>>>(out);
}

// round 17
// speedup vs baseline: 1.1049x; 1.1049x over previous
#include <cuda_runtime.h>

#define S_LEN   2048
#define NCH     64
#define NB      16
#define CHUNK   128
#define NSC     (S_LEN / CHUNK)        // 16 sample-chunks
#define PLI_THREADS 512
#define NWARPS  (PLI_THREADS / 32)
#define FFT_THREADS 512
#define N_PLI_BLOCKS (NSC * NB)        // 256 (all co-resident: 444 slots)

// Scratch (static __device__ allocation — allowed by harness rules)
__device__ float2 g_analytic[NB * NCH * S_LEN];   // 16 MB
__device__ int    g_cnt[NB * NCH * NCH];          // 256 KB of int counters
__device__ int    g_done;                         // grid-barrier counter

// ---------------------------------------------------------------------------
// Radix-4 Stockham autosort FFT pieces (N = 2048 = 2 * 4^5).
// DIF formulation; natural-order in, natural-order out; ping-pong buffers.
// ---------------------------------------------------------------------------
__device__ __forceinline__ float2 cmul(float2 a, float2 b) {
    return make_float2(fmaf(a.x, b.x, -a.y * b.y),
                       fmaf(a.x, b.y,  a.y * b.x));
}

// radix-2 first stage (forward): l = 1024, m = 1
__device__ __forceinline__ void stage_r2_fwd(const float2* __restrict__ src,
                                             float2* __restrict__ dst,
                                             const float2* __restrict__ tw,
                                             int tid) {
    #pragma unroll
    for (int p = tid; p < 1024; p += FFT_THREADS) {
        float2 w = tw[p];                       // exp(-2*pi*i p/2048)
        float2 a = src[p];
        float2 b = src[p + 1024];
        dst[2 * p]     = make_float2(a.x + b.x, a.y + b.y);
        dst[2 * p + 1] = cmul(w, make_float2(a.x - b.x, a.y - b.y));
    }
}

// radix-4 stage: L * M * 4 == 2048
template<int L, int LOG2M, bool INV>
__device__ __forceinline__ void stage_r4(const float2* __restrict__ src,
                                         float2* __restrict__ dst,
                                         const float2* __restrict__ tw,
                                         int tid) {
    constexpr int M   = 1 << LOG2M;
    constexpr int TWS = 512 / L;                // twiddle stride
    #pragma unroll
    for (int t = tid; t < 512; t += FFT_THREADS) {
        const int p = t >> LOG2M;
        const int q = t & (M - 1);
        const int ib = q + M * p;               // == t
        float2 a = src[ib];
        float2 b = src[ib + M * L];
        float2 c = src[ib + 2 * M * L];
        float2 d = src[ib + 3 * M * L];

        float2 w1 = tw[p * TWS];                // exp(-2*pi*i p/(4L))
        float2 w2 = tw[2 * p * TWS];
        if (INV) { w1.y = -w1.y; w2.y = -w2.y; }
        float2 w3 = cmul(w1, w2);

        float2 t0 = make_float2(a.x + c.x, a.y + c.y);
        float2 t1 = make_float2(a.x - c.x, a.y - c.y);
        float2 t2 = make_float2(b.x + d.x, b.y + d.y);
        float2 e  = make_float2(b.x - d.x, b.y - d.y);
        float2 t3 = INV ? make_float2(-e.y,  e.x)
                        : make_float2( e.y, -e.x);

        const int ob = q + 4 * M * p;
        dst[ob]         = make_float2(t0.x + t2.x, t0.y + t2.y);
        dst[ob + M]     = cmul(w1, make_float2(t1.x + t3.x, t1.y + t3.y));
        dst[ob + 2 * M] = cmul(w2, make_float2(t0.x - t2.x, t0.y - t2.y));
        dst[ob + 3 * M] = cmul(w3, make_float2(t1.x - t3.x, t1.y - t3.y));
    }
}

// 5 inverse radix-4 stages (after the fused degenerate stage-1).
// X -> Y -> X -> Y -> X -> Y : result lands in Y. Ends with __syncthreads.
__device__ __forceinline__ void ifft_tail(float2* __restrict__ X,
                                          float2* __restrict__ Y,
                                          const float2* __restrict__ tw,
                                          int tid) {
    stage_r4<256, 1, true>(X, Y, tw, tid);  __syncthreads();
    stage_r4< 64, 3, true>(Y, X, tw, tid);  __syncthreads();
    stage_r4< 16, 5, true>(X, Y, tw, tid);  __syncthreads();
    stage_r4<  4, 7, true>(Y, X, tw, tid);  __syncthreads();
    stage_r4<  1, 9, true>(X, Y, tw, tid);  __syncthreads();
}

// ---------------------------------------------------------------------------
// Kernel 1: Hilbert analytic signal (unchanged from R15 winner).
//   W = IFFT(h/N ⊙ FFT(x0 + i*x1));  Hx0 = Im W - x1 ,  Hx1 = x0 - Re W.
// Single inverse chain; degenerate stage-1 fused with the filter.
// Also zeroes g_cnt and g_done (stream-ordered before pli).
// ---------------------------------------------------------------------------
__global__ __launch_bounds__(FFT_THREADS)
void hilbert_kernel(const float* __restrict__ x) {
    __shared__ float2 A [S_LEN];
    __shared__ float2 B [S_LEN];
    __shared__ float2 tw[S_LEN / 2];

    const int bc  = blockIdx.x;               // 0..511 (channel pair)
    const int tid = threadIdx.x;
    const int ch0 = 2 * bc;

    if (tid < 128) g_cnt[bc * 128 + tid] = 0;
    if (bc == 0 && tid == 0) g_done = 0;

    const float* __restrict__ x0 = x + (size_t)ch0 * S_LEN;
    const float* __restrict__ x1 = x0 + S_LEN;

    for (int k = tid; k < S_LEN / 2; k += FFT_THREADS) {
        float ang = (-6.283185307179586f / (float)S_LEN) * (float)k;
        float sn, cs;
        sincosf(ang, &sn, &cs);
        tw[k] = make_float2(cs, sn);
    }
    for (int i = tid; i < S_LEN; i += FFT_THREADS)
        A[i] = make_float2(x0[i], x1[i]);
    __syncthreads();

    stage_r2_fwd(A, B, tw, tid);               __syncthreads();
    stage_r4<256, 1, false>(B, A, tw, tid);    __syncthreads();
    stage_r4< 64, 3, false>(A, B, tw, tid);    __syncthreads();
    stage_r4< 16, 5, false>(B, A, tw, tid);    __syncthreads();
    stage_r4<  4, 7, false>(A, B, tw, tid);    __syncthreads();
    stage_r4<  1, 9, false>(B, A, tw, tid);    __syncthreads();

    const float S0 = 1.0f / 2048.0f;
    const float S1 = 2.0f / 2048.0f;
    for (int p = tid; p < 1024; p += FFT_THREADS) {
        if (p == 0) {
            float2 z0 = A[0];
            float2 zn = A[1024];
            float2 W0 = make_float2(z0.x * S0, z0.y * S0);
            float2 Wn = make_float2(zn.x * S0, zn.y * S0);
            B[0] = make_float2(W0.x + Wn.x, W0.y + Wn.y);
            B[1] = make_float2(W0.x - Wn.x, W0.y - Wn.y);
        } else {
            float2 zp = A[p];
            float2 Wp = make_float2(zp.x * S1, zp.y * S1);
            float2 wc = tw[p]; wc.y = -wc.y;
            B[2 * p]     = Wp;
            B[2 * p + 1] = cmul(wc, Wp);
        }
    }
    __syncthreads();

    ifft_tail(B, A, tw, tid);

    float2* __restrict__ d0 = g_analytic + (size_t)ch0 * S_LEN;
    float2* __restrict__ d1 = d0 + S_LEN;
    for (int i = tid; i < S_LEN; i += FFT_THREADS) {
        float2 W  = A[i];
        float  r0 = x0[i];
        float  r1 = x1[i];
        d0[i] = make_float2(r0, W.y - r1);
        d1[i] = make_float2(r1, r0 - W.x);
    }
}

// ---------------------------------------------------------------------------
// Kernel 2: pairwise sign counting (R15's proven scalar inner loop) + grid
// barrier + distributed finalize. All 256 blocks are co-resident (64 KB smem
// -> 3 blocks/SM x 148 = 444 slots), so the spin on g_done cannot deadlock.
// After the barrier each block writes its own 256-element output slice.
// ---------------------------------------------------------------------------
__global__ __launch_bounds__(PLI_THREADS)
void pli_kernel(float* __restrict__ out) {
    extern __shared__ float2 sdata[];                 // [NCH][CHUNK]
    const int sc  = blockIdx.x;
    const int b   = blockIdx.y;
    const int tid = threadIdx.x;

    const float4* gsrc = reinterpret_cast<const float4*>(g_analytic);
    float4* ssh = reinterpret_cast<float4*>(sdata);
    for (int k = tid; k < NCH * (CHUNK / 2); k += PLI_THREADS) {
        int c  = k / (CHUNK / 2);
        int sp = k - c * (CHUNK / 2);
        size_t gi = (((size_t)(b * NCH + c)) * S_LEN + (size_t)sc * CHUNK) / 2 + sp;
        ssh[c * (CHUNK / 2) + sp] = gsrc[gi];
    }
    __syncthreads();

    const int warp = tid >> 5;
    const int lane = tid & 31;

    for (int t = warp; t < 136; t += NWARPS) {
        int ti = 0, rem = t;
        while (rem >= (16 - ti)) { rem -= (16 - ti); ti++; }
        int tj = ti + rem;

        const float2* rowi = sdata + (ti * 4) * CHUNK;
        const float2* rowj = sdata + (tj * 4) * CHUNK;

        unsigned acc[16];
        #pragma unroll
        for (int q = 0; q < 16; q++) acc[q] = 0u;

        #pragma unroll
        for (int it = 0; it < CHUNK / 32; it++) {
            int s = it * 32 + lane;
            float2 ai[4], aj[4];
            #pragma unroll
            for (int a = 0; a < 4; a++) ai[a] = rowi[a * CHUNK + s];
            #pragma unroll
            for (int a = 0; a < 4; a++) aj[a] = rowj[a * CHUNK + s];

            #pragma unroll
            for (int a = 0; a < 4; a++) {
                #pragma unroll
                for (int c2 = 0; c2 < 4; c2++) {
                    float p     = ai[a].x * aj[c2].y;
                    float cross = fmaf(ai[a].y, aj[c2].x, -p);
                    // negative (sign bit) => sin < 0 ; exact zeros measure-zero
                    acc[a * 4 + c2] += __float_as_uint(cross) >> 31;
                }
            }
        }

        #pragma unroll
        for (int q = 0; q < 16; q++)
            acc[q] = __reduce_add_sync(0xffffffffu, acc[q]);

        if (lane == 0) {
            #pragma unroll
            for (int a = 0; a < 4; a++) {
                #pragma unroll
                for (int c2 = 0; c2 < 4; c2++) {
                    atomicAdd(&g_cnt[(b * NCH + ti * 4 + a) * NCH + tj * 4 + c2],
                              (int)acc[a * 4 + c2]);
                }
            }
        }
    }

    // ---- grid barrier (all blocks resident) + distributed finalize ----
    __syncthreads();
    if (tid == 0) {
        __threadfence();                       // publish this block's atomics
        atomicAdd(&g_done, 1);
        while (atomicAdd(&g_done, 0) < N_PLI_BLOCKS) { }   // spin
    }
    __syncthreads();
    __threadfence();                           // acquire all blocks' counts

    // each block writes its 256-element slice of the 65536-element output
    const int blk  = b * NSC + sc;             // 0..255
    const int base = blk * 256;
    for (int k = tid; k < 256; k += PLI_THREADS) {
        int idx = base + k;
        int bb = idx >> 12;
        int i  = (idx >> 6) & 63;
        int j  = idx & 63;
        float v = 0.0f;
        if (i != j) {
            int c = (i < j) ? g_cnt[(bb * NCH + i) * NCH + j]
                            : g_cnt[(bb * NCH + j) * NCH + i];
            v = fabsf(2.0f * (float)c - (float)S_LEN) * (1.0f / (float)S_LEN);
        }
        out[idx] = v;
    }
}

// ---------------------------------------------------------------------------
extern "C" void kernel_launch(void* const* d_in, const int* in_sizes, int n_in,
                              void* d_out, int out_size) {
    const float* x = (const float*)d_in[0];
    float* out = (float*)d_out;
    (void)in_sizes; (void)n_in; (void)out_size;

    const int pli_smem = NCH * CHUNK * (int)sizeof(float2);   // 64 KB
    cudaFuncSetAttribute(pli_kernel,
                         cudaFuncAttributeMaxDynamicSharedMemorySize, pli_smem);

    hilbert_kernel<<<NB * NCH / 2, FFT_THREADS>>>(x);
    pli_kernel<<<dim3(NSC, NB), PLI_THREADS, pli_smem>>>(out);
}